// round 1
// baseline (speedup 1.0000x reference)
#include <cuda_runtime.h>
#include <cuda_bf16.h>

// Problem constants (from reference_code)
#define NS   50000
#define D    128
#define H    128
#define ESS  800000

// ---------------- device scratch (static, no allocations) ----------------
__device__ int   g_cnt[NS];
__device__ int   g_off[NS + 1];
__device__ int   g_cur[NS];
__device__ int   g_csr[ESS];
__device__ float g_agg[(size_t)NS * H];
__device__ float g_s1 [(size_t)NS * H];
__device__ float g_s2 [(size_t)NS * H];

// ---------------- small utility kernels ----------------
__global__ void zero_int_kernel(int* p, int n) {
    int i = blockIdx.x * blockDim.x + threadIdx.x;
    if (i < n) p[i] = 0;
}

__global__ void hist_kernel(const int* __restrict__ dst, int* __restrict__ cnt, int n) {
    int i = blockIdx.x * blockDim.x + threadIdx.x;
    if (i < n) atomicAdd(&cnt[dst[i]], 1);
}

// single-block exclusive scan over NS elements -> offsets + cursor init
__global__ void scan_kernel(const int* __restrict__ cnt, int* __restrict__ off,
                            int* __restrict__ cur) {
    __shared__ int partial[1024];
    const int tid = threadIdx.x;
    const int C = (NS + 1023) / 1024;   // 49
    const int base = tid * C;

    int sum = 0;
    for (int i = 0; i < C; i++) {
        int idx = base + i;
        if (idx < NS) sum += cnt[idx];
    }
    partial[tid] = sum;
    __syncthreads();
    // Hillis-Steele inclusive scan
    for (int d = 1; d < 1024; d <<= 1) {
        int v = 0;
        if (tid >= d) v = partial[tid - d];
        __syncthreads();
        if (tid >= d) partial[tid] += v;
        __syncthreads();
    }
    int prefix = (tid == 0) ? 0 : partial[tid - 1];
    for (int i = 0; i < C; i++) {
        int idx = base + i;
        if (idx < NS) {
            off[idx] = prefix;
            cur[idx] = prefix;
            prefix += cnt[idx];
        }
    }
    if (tid == 1023) off[NS] = prefix;   // == total (tail chunks contribute 0)
}

__global__ void scatter_kernel(const int* __restrict__ src, const int* __restrict__ dst,
                               int* __restrict__ cur, int* __restrict__ csr, int n) {
    int i = blockIdx.x * blockDim.x + threadIdx.x;
    if (i < n) {
        int p = atomicAdd(&cur[dst[i]], 1);
        csr[p] = src[i];
    }
}

// mean aggregation: one block per node, one thread per feature
__global__ void agg_kernel(const float* __restrict__ x, const int* __restrict__ off,
                           const int* __restrict__ csr, float* __restrict__ out) {
    int node = blockIdx.x;
    int f    = threadIdx.x;
    int s = off[node], e = off[node + 1];
    float acc = 0.f;
    for (int i = s; i < e; i++) {
        int src = __ldg(&csr[i]);
        acc += __ldg(&x[(size_t)src * H + f]);
    }
    float inv = (e > s) ? (1.0f / (float)(e - s)) : 0.0f;
    out[(size_t)node * H + f] = acc * inv;
}

// fused SAGE GEMM: out = relu([agg | xin](M x 256) @ [Wl;Wr](256x128) + bias)
// block: 256 threads, tile: 64 rows x 128 cols (full N), persistent over tiles
__global__ void gemm_kernel(const float* __restrict__ agg, const float* __restrict__ xin,
                            const float* __restrict__ Wl, const float* __restrict__ Wr,
                            const float* __restrict__ bias, float* __restrict__ out, int M) {
    extern __shared__ float sm[];
    float* Ws = sm;               // [256][128]
    float* As = sm + 256 * 128;   // [64][256]
    const int tid = threadIdx.x;

    // stage combined weights [Wl ; Wr] once per block
    #pragma unroll 4
    for (int i = tid; i < (256 * 128) / 4; i += 256) {
        int idx = i * 4;
        int k = idx >> 7;          // 0..255
        int n = idx & 127;
        const float* wsrc = (k < 128) ? (Wl + (size_t)k * 128 + n)
                                      : (Wr + (size_t)(k - 128) * 128 + n);
        *(float4*)(Ws + idx) = *(const float4*)wsrc;
    }
    __syncthreads();

    const int ct = tid & 31;       // col-thread: 32 -> covers N=128 in float4s
    const int rt = tid >> 5;       // row-thread: 8  -> covers 64 rows in groups of 8
    const int n0 = ct * 4;
    const int r0 = rt * 8;
    const float b0 = bias[n0], b1 = bias[n0 + 1], b2 = bias[n0 + 2], b3 = bias[n0 + 3];

    const int ntiles = (M + 63) >> 6;
    for (int tile = blockIdx.x; tile < ntiles; tile += gridDim.x) {
        const int row0 = tile << 6;
        const int rows = min(64, M - row0);

        // stage A tile: [64][256] = [agg | xin]
        #pragma unroll 2
        for (int i = tid; i < (64 * 256) / 4; i += 256) {
            int idx = i * 4;
            int r = idx >> 8;
            int k = idx & 255;
            float4 v = make_float4(0.f, 0.f, 0.f, 0.f);
            if (r < rows) {
                const float* src = (k < 128) ? (agg + (size_t)(row0 + r) * 128 + k)
                                             : (xin + (size_t)(row0 + r) * 128 + (k - 128));
                v = *(const float4*)src;
            }
            *(float4*)(As + idx) = v;
        }
        __syncthreads();

        float acc[8][4];
        #pragma unroll
        for (int i = 0; i < 8; i++)
            #pragma unroll
            for (int j = 0; j < 4; j++) acc[i][j] = 0.f;

        #pragma unroll 4
        for (int k = 0; k < 256; k++) {
            float4 w = *(float4*)(Ws + k * 128 + n0);
            #pragma unroll
            for (int i = 0; i < 8; i++) {
                float a = As[(r0 + i) * 256 + k];
                acc[i][0] = fmaf(a, w.x, acc[i][0]);
                acc[i][1] = fmaf(a, w.y, acc[i][1]);
                acc[i][2] = fmaf(a, w.z, acc[i][2]);
                acc[i][3] = fmaf(a, w.w, acc[i][3]);
            }
        }

        // epilogue: bias + relu, store
        #pragma unroll
        for (int i = 0; i < 8; i++) {
            int r = r0 + i;
            if (r < rows) {
                float4 v;
                v.x = fmaxf(acc[i][0] + b0, 0.f);
                v.y = fmaxf(acc[i][1] + b1, 0.f);
                v.z = fmaxf(acc[i][2] + b2, 0.f);
                v.w = fmaxf(acc[i][3] + b3, 0.f);
                *(float4*)(out + (size_t)(row0 + r) * 128 + n0) = v;
            }
        }
        __syncthreads();   // before As is overwritten next tile
    }
}

// out(M x 2) = s2(M x 128) @ lin_w(128 x 2) + lin_b(2)
__global__ void lin_kernel(const float* __restrict__ s2, const float* __restrict__ lw,
                           const float* __restrict__ lb, float* __restrict__ out, int M) {
    __shared__ float w[256];
    if (threadIdx.x < 256) w[threadIdx.x] = lw[threadIdx.x];
    __syncthreads();
    int r = blockIdx.x * blockDim.x + threadIdx.x;
    if (r >= M) return;
    float a0 = 0.f, a1 = 0.f;
    const float4* row = (const float4*)(s2 + (size_t)r * 128);
    #pragma unroll
    for (int i = 0; i < 32; i++) {
        float4 v = row[i];
        int k = i * 4;
        a0 += v.x * w[(k + 0) * 2 + 0] + v.y * w[(k + 1) * 2 + 0]
            + v.z * w[(k + 2) * 2 + 0] + v.w * w[(k + 3) * 2 + 0];
        a1 += v.x * w[(k + 0) * 2 + 1] + v.y * w[(k + 1) * 2 + 1]
            + v.z * w[(k + 2) * 2 + 1] + v.w * w[(k + 3) * 2 + 1];
    }
    out[(size_t)r * 2 + 0] = a0 + lb[0];
    out[(size_t)r * 2 + 1] = a1 + lb[1];
}

// ---------------- host launcher ----------------
extern "C" void kernel_launch(void* const* d_in, const int* in_sizes, int n_in,
                              void* d_out, int out_size) {
    // Classify inputs by element count. The relative order of same-sized inputs
    // (weights: ..._l before ..._r, layer1 before layer2; biases b1_* then b2_*;
    // ss_src before ss_dst) is identical under both the reference-signature
    // order and the setup_inputs dict order, so ordinal matching is safe.
    const float* x_subject = nullptr;
    const float* wlist[12] = {};
    const float* blist[6]  = {};
    const float* lin_w = nullptr;
    const float* lin_b = nullptr;
    const int*   ss_src = nullptr;
    const int*   ss_dst = nullptr;
    int wc = 0, bc = 0;
    for (int i = 0; i < n_in; i++) {
        int sz = in_sizes[i];
        if      (sz == NS * D)              x_subject = (const float*)d_in[i];
        else if (sz == 128 * 128 && wc < 12) wlist[wc++] = (const float*)d_in[i];
        else if (sz == 128 && bc < 6)        blist[bc++] = (const float*)d_in[i];
        else if (sz == 128 * 2)              lin_w = (const float*)d_in[i];
        else if (sz == 2)                    lin_b = (const float*)d_in[i];
        else if (sz == ESS) {
            if (!ss_src) ss_src = (const int*)d_in[i];
            else         ss_dst = (const int*)d_in[i];
        }
        // sizes NR*D (x_roi), 1000000 (sr edges), 1600000 (rr edges): dead code, ignored
    }
    // weight ordinal map (both orderings):
    // [w1_sr_l, w1_sr_r, w1_rr_l, w1_rr_r, w1_ss_l, w1_ss_r,
    //  w2_sr_l, w2_sr_r, w2_rr_l, w2_rr_r, w2_ss_l, w2_ss_r]
    const float* w1_ss_l = wlist[4];
    const float* w1_ss_r = wlist[5];
    const float* w2_ss_l = wlist[10];
    const float* w2_ss_r = wlist[11];
    // bias ordinal map: [b1_sr, b1_rr, b1_ss, b2_sr, b2_rr, b2_ss]
    const float* b1_ss = blist[2];
    const float* b2_ss = blist[5];

    void *p_cnt, *p_off, *p_cur, *p_csr, *p_agg, *p_s1, *p_s2;
    cudaGetSymbolAddress(&p_cnt, g_cnt);
    cudaGetSymbolAddress(&p_off, g_off);
    cudaGetSymbolAddress(&p_cur, g_cur);
    cudaGetSymbolAddress(&p_csr, g_csr);
    cudaGetSymbolAddress(&p_agg, g_agg);
    cudaGetSymbolAddress(&p_s1,  g_s1);
    cudaGetSymbolAddress(&p_s2,  g_s2);
    int*   cnt = (int*)p_cnt;
    int*   off = (int*)p_off;
    int*   cur = (int*)p_cur;
    int*   csr = (int*)p_csr;
    float* agg = (float*)p_agg;
    float* s1  = (float*)p_s1;
    float* s2  = (float*)p_s2;
    float* out = (float*)d_out;

    const int GEMM_SMEM = (256 * 128 + 64 * 256) * (int)sizeof(float);  // 192 KB
    cudaFuncSetAttribute(gemm_kernel, cudaFuncAttributeMaxDynamicSharedMemorySize, GEMM_SMEM);

    // ---- CSR build (once; both layers use the same ss edge list) ----
    zero_int_kernel<<<(NS + 255) / 256, 256>>>(cnt, NS);
    hist_kernel<<<(ESS + 255) / 256, 256>>>(ss_dst, cnt, ESS);
    scan_kernel<<<1, 1024>>>(cnt, off, cur);
    scatter_kernel<<<(ESS + 255) / 256, 256>>>(ss_src, ss_dst, cur, csr, ESS);

    // ---- layer 1 ----
    agg_kernel<<<NS, 128>>>(x_subject, off, csr, agg);
    gemm_kernel<<<148, 256, GEMM_SMEM>>>(agg, x_subject, w1_ss_l, w1_ss_r, b1_ss, s1, NS);

    // ---- layer 2 ----
    agg_kernel<<<NS, 128>>>(s1, off, csr, agg);
    gemm_kernel<<<148, 256, GEMM_SMEM>>>(agg, s1, w2_ss_l, w2_ss_r, b2_ss, s2, NS);

    // ---- output projection ----
    lin_kernel<<<(NS + 255) / 256, 256>>>(s2, lin_w, lin_b, out, NS);
}

// round 3
// speedup vs baseline: 1.3100x; 1.3100x over previous
#include <cuda_runtime.h>
#include <cuda_bf16.h>
#include <cstdint>

// Problem constants (from reference_code)
#define NS   50000
#define D    128
#define H    128
#define ESS  800000

// ---------------- device scratch (static, no allocations) ----------------
__device__ int   g_cnt[NS];
__device__ int   g_off[NS + 1];
__device__ int   g_cur[NS];
__device__ int   g_csr[ESS];
__device__ float g_agg[(size_t)NS * H];
__device__ float g_s1 [(size_t)NS * H];
__device__ float g_s2 [(size_t)NS * H];

// ---------------- small utility kernels ----------------
__global__ void zero_int_kernel(int* p, int n) {
    int i = blockIdx.x * blockDim.x + threadIdx.x;
    if (i < n) p[i] = 0;
}

__global__ void hist_kernel(const int* __restrict__ dst, int* __restrict__ cnt, int n) {
    int i = blockIdx.x * blockDim.x + threadIdx.x;
    if (i < n) atomicAdd(&cnt[dst[i]], 1);
}

// single-block exclusive scan over NS elements -> offsets + cursor init
__global__ void scan_kernel(const int* __restrict__ cnt, int* __restrict__ off,
                            int* __restrict__ cur) {
    __shared__ int partial[1024];
    const int tid = threadIdx.x;
    const int C = (NS + 1023) / 1024;   // 49
    const int base = tid * C;

    int sum = 0;
    for (int i = 0; i < C; i++) {
        int idx = base + i;
        if (idx < NS) sum += cnt[idx];
    }
    partial[tid] = sum;
    __syncthreads();
    for (int d = 1; d < 1024; d <<= 1) {
        int v = 0;
        if (tid >= d) v = partial[tid - d];
        __syncthreads();
        if (tid >= d) partial[tid] += v;
        __syncthreads();
    }
    int prefix = (tid == 0) ? 0 : partial[tid - 1];
    for (int i = 0; i < C; i++) {
        int idx = base + i;
        if (idx < NS) {
            off[idx] = prefix;
            cur[idx] = prefix;
            prefix += cnt[idx];
        }
    }
    if (tid == 1023) off[NS] = prefix;
}

__global__ void scatter_kernel(const int* __restrict__ src, const int* __restrict__ dst,
                               int* __restrict__ cur, int* __restrict__ csr, int n) {
    int i = blockIdx.x * blockDim.x + threadIdx.x;
    if (i < n) {
        int p = atomicAdd(&cur[dst[i]], 1);
        csr[p] = src[i];
    }
}

// mean aggregation: one block per node, one thread per feature, 2-way edge ILP
__global__ void agg_kernel(const float* __restrict__ x, const int* __restrict__ off,
                           const int* __restrict__ csr, float* __restrict__ out) {
    int node = blockIdx.x;
    int f    = threadIdx.x;
    int s = off[node], e = off[node + 1];
    float acc = 0.f;
    int i = s;
    for (; i + 1 < e; i += 2) {
        int s0 = __ldg(&csr[i]);
        int s1 = __ldg(&csr[i + 1]);
        float a = __ldg(&x[(size_t)s0 * H + f]);
        float b = __ldg(&x[(size_t)s1 * H + f]);
        acc += a + b;
    }
    if (i < e) {
        int s0 = __ldg(&csr[i]);
        acc += __ldg(&x[(size_t)s0 * H + f]);
    }
    float inv = (e > s) ? (1.0f / (float)(e - s)) : 0.0f;
    out[(size_t)node * H + f] = acc * inv;
}

// ================= HMMA (mma.sync bf16) GEMM =================
// out = relu([agg | xin](M x 256) @ [Wl;Wr](256 x 128) + bias)
// per CTA: 128 rows x 128 cols, K=256 as 2 chunks of 128.
// fp32 -> bf16 hi/lo split, 3 passes (hi*hi, hi*lo, lo*hi).

#define TC_THREADS 256
// smem byte offsets (row stride 272B = 136 bf16 to kill ldmatrix bank conflicts)
#define RS      272
#define SMEM_BIAS_OFF 0
#define SMEM_AH 512
#define SMEM_AL (SMEM_AH + 128 * RS)
#define SMEM_BH (SMEM_AL + 128 * RS)
#define SMEM_BL (SMEM_BH + 128 * RS)
#define SMEM_TOTAL (SMEM_BL + 128 * RS)   // 512 + 4*34816 = 139776

__device__ __forceinline__ uint32_t smem_u32(const void* p) {
    uint32_t a;
    asm("{ .reg .u64 t; cvta.to.shared.u64 t, %1; cvt.u32.u64 %0, t; }" : "=r"(a) : "l"(p));
    return a;
}

__device__ __forceinline__ uint32_t pack_bf16x2(float lo_val, float hi_val) {
    __nv_bfloat162 h = __floats2bfloat162_rn(lo_val, hi_val);
    return *(uint32_t*)&h;
}

__device__ __forceinline__ void ldsm_x4(uint32_t& r0, uint32_t& r1, uint32_t& r2,
                                        uint32_t& r3, uint32_t addr) {
    asm volatile("ldmatrix.sync.aligned.m8n8.x4.shared.b16 {%0,%1,%2,%3}, [%4];"
                 : "=r"(r0), "=r"(r1), "=r"(r2), "=r"(r3) : "r"(addr));
}

__device__ __forceinline__ void ldsm_x4_t(uint32_t& r0, uint32_t& r1, uint32_t& r2,
                                          uint32_t& r3, uint32_t addr) {
    asm volatile("ldmatrix.sync.aligned.m8n8.x4.trans.shared.b16 {%0,%1,%2,%3}, [%4];"
                 : "=r"(r0), "=r"(r1), "=r"(r2), "=r"(r3) : "r"(addr));
}

__device__ __forceinline__ void mma16816(float* c, uint32_t a0, uint32_t a1, uint32_t a2,
                                         uint32_t a3, uint32_t b0, uint32_t b1) {
    asm volatile(
        "mma.sync.aligned.m16n8k16.row.col.f32.bf16.bf16.f32 "
        "{%0,%1,%2,%3}, {%4,%5,%6,%7}, {%8,%9}, {%0,%1,%2,%3};"
        : "+f"(c[0]), "+f"(c[1]), "+f"(c[2]), "+f"(c[3])
        : "r"(a0), "r"(a1), "r"(a2), "r"(a3), "r"(b0), "r"(b1));
}

__global__ void __launch_bounds__(TC_THREADS, 1)
gemm_mma_kernel(const float* __restrict__ agg, const float* __restrict__ xin,
                const float* __restrict__ Wl, const float* __restrict__ Wr,
                const float* __restrict__ bias, float* __restrict__ out, int M) {
    extern __shared__ char sm[];
    const uint32_t sb = smem_u32(sm);
    const int tid  = threadIdx.x;
    const int wid  = tid >> 5;
    const int lane = tid & 31;
    const int warp_m = wid & 3;   // 4 row-warps, 32 rows each
    const int warp_n = wid >> 2;  // 2 col-warps, 64 cols each
    const int row0 = blockIdx.x << 7;

    if (tid < 128) ((float*)(sm + SMEM_BIAS_OFF))[tid] = bias[tid];

    // per-lane ldmatrix address components
    const uint32_t a_lane = (uint32_t)((lane & 15) * RS + ((lane >> 4) << 4));
    const uint32_t b_lane = (uint32_t)((((lane & 7) + ((lane >> 3) & 1) * 8)) * RS
                                       + ((lane >> 4) << 4));
    const uint32_t a_warp = (uint32_t)(warp_m * 32 * RS);   // + mt*16*RS
    const uint32_t b_warp = (uint32_t)(warp_n * 64 * 2);    // + nt*16*2

    float c[2][8][4];
    #pragma unroll
    for (int i = 0; i < 2; i++)
        #pragma unroll
        for (int j = 0; j < 8; j++)
            #pragma unroll
            for (int q = 0; q < 4; q++) c[i][j][q] = 0.f;

    for (int chunk = 0; chunk < 2; chunk++) {
        const float* Asrc = chunk ? xin : agg;
        const float* Bsrc = chunk ? Wr  : Wl;

        // stage A: 128 rows x 128 k (hi/lo bf16)
        for (int i = tid; i < 128 * 64; i += TC_THREADS) {
            int m  = i >> 6;
            int kk = (i & 63) << 1;
            float2 v = make_float2(0.f, 0.f);
            if (row0 + m < M)
                v = *(const float2*)(Asrc + (size_t)(row0 + m) * 128 + kk);
            float hx = __bfloat162float(__float2bfloat16_rn(v.x));
            float hy = __bfloat162float(__float2bfloat16_rn(v.y));
            uint32_t off = (uint32_t)(m * RS + kk * 2);
            *(uint32_t*)(sm + SMEM_AH + off) = pack_bf16x2(hx, hy);
            *(uint32_t*)(sm + SMEM_AL + off) = pack_bf16x2(v.x - hx, v.y - hy);
        }
        // stage B: W[k][n], 128 x 128 (hi/lo bf16), same [row=k][col=n] layout
        for (int i = tid; i < 128 * 64; i += TC_THREADS) {
            int k = i >> 6;
            int n = (i & 63) << 1;
            float2 v = *(const float2*)(Bsrc + (size_t)k * 128 + n);
            float hx = __bfloat162float(__float2bfloat16_rn(v.x));
            float hy = __bfloat162float(__float2bfloat16_rn(v.y));
            uint32_t off = (uint32_t)(k * RS + n * 2);
            *(uint32_t*)(sm + SMEM_BH + off) = pack_bf16x2(hx, hy);
            *(uint32_t*)(sm + SMEM_BL + off) = pack_bf16x2(v.x - hx, v.y - hy);
        }
        __syncthreads();

        #pragma unroll
        for (int p = 0; p < 3; p++) {
            const uint32_t abuf = sb + ((p == 2) ? SMEM_AL : SMEM_AH);
            const uint32_t bbuf = sb + ((p == 1) ? SMEM_BL : SMEM_BH);
            #pragma unroll
            for (int ks = 0; ks < 8; ks++) {
                // A fragments for both 16-row m-tiles
                uint32_t a[2][4];
                #pragma unroll
                for (int mt = 0; mt < 2; mt++) {
                    uint32_t addr = abuf + a_warp + (uint32_t)(mt * 16 * RS)
                                    + (uint32_t)(ks * 32) + a_lane;
                    ldsm_x4(a[mt][0], a[mt][1], a[mt][2], a[mt][3], addr);
                }
                // B: 4 n16-tiles
                #pragma unroll
                for (int nt = 0; nt < 4; nt++) {
                    uint32_t b0, b1, b2, b3;
                    uint32_t addr = bbuf + (uint32_t)(ks * 16 * RS) + b_warp
                                    + (uint32_t)(nt * 32) + b_lane;
                    ldsm_x4_t(b0, b1, b2, b3, addr);
                    #pragma unroll
                    for (int mt = 0; mt < 2; mt++) {
                        mma16816(c[mt][nt * 2 + 0], a[mt][0], a[mt][1], a[mt][2], a[mt][3],
                                 b0, b1);
                        mma16816(c[mt][nt * 2 + 1], a[mt][0], a[mt][1], a[mt][2], a[mt][3],
                                 b2, b3);
                    }
                }
            }
        }
        __syncthreads();   // before restage
    }

    // epilogue: bias + relu, direct global stores
    const float* sbias = (const float*)(sm + SMEM_BIAS_OFF);
    const int g = lane >> 2;
    const int t = lane & 3;
    #pragma unroll
    for (int nt8 = 0; nt8 < 8; nt8++) {
        int col = warp_n * 64 + nt8 * 8 + t * 2;
        float b0 = sbias[col], b1 = sbias[col + 1];
        #pragma unroll
        for (int mt = 0; mt < 2; mt++) {
            int r_hi = row0 + warp_m * 32 + mt * 16 + g;
            if (r_hi < M) {
                float2 v;
                v.x = fmaxf(c[mt][nt8][0] + b0, 0.f);
                v.y = fmaxf(c[mt][nt8][1] + b1, 0.f);
                *(float2*)(out + (size_t)r_hi * 128 + col) = v;
            }
            int r_lo = r_hi + 8;
            if (r_lo < M) {
                float2 v;
                v.x = fmaxf(c[mt][nt8][2] + b0, 0.f);
                v.y = fmaxf(c[mt][nt8][3] + b1, 0.f);
                *(float2*)(out + (size_t)r_lo * 128 + col) = v;
            }
        }
    }
}

// out(M x 2) = s2(M x 128) @ lin_w(128 x 2) + lin_b(2)
__global__ void lin_kernel(const float* __restrict__ s2, const float* __restrict__ lw,
                           const float* __restrict__ lb, float* __restrict__ out, int M) {
    __shared__ float w[256];
    if (threadIdx.x < 256) w[threadIdx.x] = lw[threadIdx.x];
    __syncthreads();
    int r = blockIdx.x * blockDim.x + threadIdx.x;
    if (r >= M) return;
    float a0 = 0.f, a1 = 0.f;
    const float4* row = (const float4*)(s2 + (size_t)r * 128);
    #pragma unroll
    for (int i = 0; i < 32; i++) {
        float4 v = row[i];
        int k = i * 4;
        a0 += v.x * w[(k + 0) * 2 + 0] + v.y * w[(k + 1) * 2 + 0]
            + v.z * w[(k + 2) * 2 + 0] + v.w * w[(k + 3) * 2 + 0];
        a1 += v.x * w[(k + 0) * 2 + 1] + v.y * w[(k + 1) * 2 + 1]
            + v.z * w[(k + 2) * 2 + 1] + v.w * w[(k + 3) * 2 + 1];
    }
    out[(size_t)r * 2 + 0] = a0 + lb[0];
    out[(size_t)r * 2 + 1] = a1 + lb[1];
}

// ---------------- host launcher ----------------
extern "C" void kernel_launch(void* const* d_in, const int* in_sizes, int n_in,
                              void* d_out, int out_size) {
    const float* x_subject = nullptr;
    const float* wlist[12] = {};
    const float* blist[6]  = {};
    const float* lin_w = nullptr;
    const float* lin_b = nullptr;
    const int*   ss_src = nullptr;
    const int*   ss_dst = nullptr;
    int wc = 0, bc = 0;
    for (int i = 0; i < n_in; i++) {
        int sz = in_sizes[i];
        if      (sz == NS * D)              x_subject = (const float*)d_in[i];
        else if (sz == 128 * 128 && wc < 12) wlist[wc++] = (const float*)d_in[i];
        else if (sz == 128 && bc < 6)        blist[bc++] = (const float*)d_in[i];
        else if (sz == 128 * 2)              lin_w = (const float*)d_in[i];
        else if (sz == 2)                    lin_b = (const float*)d_in[i];
        else if (sz == ESS) {
            if (!ss_src) ss_src = (const int*)d_in[i];
            else         ss_dst = (const int*)d_in[i];
        }
    }
    const float* w1_ss_l = wlist[4];
    const float* w1_ss_r = wlist[5];
    const float* w2_ss_l = wlist[10];
    const float* w2_ss_r = wlist[11];
    const float* b1_ss = blist[2];
    const float* b2_ss = blist[5];

    void *p_cnt, *p_off, *p_cur, *p_csr, *p_agg, *p_s1, *p_s2;
    cudaGetSymbolAddress(&p_cnt, g_cnt);
    cudaGetSymbolAddress(&p_off, g_off);
    cudaGetSymbolAddress(&p_cur, g_cur);
    cudaGetSymbolAddress(&p_csr, g_csr);
    cudaGetSymbolAddress(&p_agg, g_agg);
    cudaGetSymbolAddress(&p_s1,  g_s1);
    cudaGetSymbolAddress(&p_s2,  g_s2);
    int*   cnt = (int*)p_cnt;
    int*   off = (int*)p_off;
    int*   cur = (int*)p_cur;
    int*   csr = (int*)p_csr;
    float* agg = (float*)p_agg;
    float* s1  = (float*)p_s1;
    float* s2  = (float*)p_s2;
    float* out = (float*)d_out;

    cudaFuncSetAttribute(gemm_mma_kernel, cudaFuncAttributeMaxDynamicSharedMemorySize,
                         SMEM_TOTAL);

    const int NTILES = (NS + 127) / 128;   // 391

    // ---- CSR build (once; both layers use the same ss edge list) ----
    zero_int_kernel<<<(NS + 255) / 256, 256>>>(cnt, NS);
    hist_kernel<<<(ESS + 255) / 256, 256>>>(ss_dst, cnt, ESS);
    scan_kernel<<<1, 1024>>>(cnt, off, cur);
    scatter_kernel<<<(ESS + 255) / 256, 256>>>(ss_src, ss_dst, cur, csr, ESS);

    // ---- layer 1 ----
    agg_kernel<<<NS, 128>>>(x_subject, off, csr, agg);
    gemm_mma_kernel<<<NTILES, TC_THREADS, SMEM_TOTAL>>>(agg, x_subject, w1_ss_l, w1_ss_r,
                                                        b1_ss, s1, NS);

    // ---- layer 2 ----
    agg_kernel<<<NS, 128>>>(s1, off, csr, agg);
    gemm_mma_kernel<<<NTILES, TC_THREADS, SMEM_TOTAL>>>(agg, s1, w2_ss_l, w2_ss_r,
                                                        b2_ss, s2, NS);

    // ---- output projection ----
    lin_kernel<<<(NS + 255) / 256, 256>>>(s2, lin_w, lin_b, out, NS);
}

// round 4
// speedup vs baseline: 1.7828x; 1.3609x over previous
#include <cuda_runtime.h>
#include <cuda_bf16.h>
#include <cstdint>

// Problem constants (from reference_code)
#define NS   50000
#define D    128
#define H    128
#define ESS  800000

// ---------------- device scratch (static, no allocations) ----------------
__device__ int   g_cnt[NS];
__device__ int   g_off[NS + 1];
__device__ int   g_cur[NS];
__device__ int   g_csr[ESS];
__device__ float g_agg[(size_t)NS * H];
__device__ float g_s1 [(size_t)NS * H];
__device__ __nv_bfloat16 g_wh[2][256 * 128];
__device__ __nv_bfloat16 g_wl[2][256 * 128];

// ---------------- small utility kernels ----------------
__global__ void zero_int_kernel(int* p, int n) {
    int i = blockIdx.x * blockDim.x + threadIdx.x;
    if (i < n) p[i] = 0;
}

__global__ void hist_kernel(const int* __restrict__ dst, int* __restrict__ cnt, int n) {
    int i = blockIdx.x * blockDim.x + threadIdx.x;
    if (i < n) atomicAdd(&cnt[dst[i]], 1);
}

// single-block exclusive scan over NS elements -> offsets + cursor init
__global__ void scan_kernel(const int* __restrict__ cnt, int* __restrict__ off,
                            int* __restrict__ cur) {
    __shared__ int partial[1024];
    const int tid = threadIdx.x;
    const int C = (NS + 1023) / 1024;   // 49
    const int base = tid * C;

    int sum = 0;
    for (int i = 0; i < C; i++) {
        int idx = base + i;
        if (idx < NS) sum += cnt[idx];
    }
    partial[tid] = sum;
    __syncthreads();
    for (int d = 1; d < 1024; d <<= 1) {
        int v = 0;
        if (tid >= d) v = partial[tid - d];
        __syncthreads();
        if (tid >= d) partial[tid] += v;
        __syncthreads();
    }
    int prefix = (tid == 0) ? 0 : partial[tid - 1];
    for (int i = 0; i < C; i++) {
        int idx = base + i;
        if (idx < NS) {
            off[idx] = prefix;
            cur[idx] = prefix;
            prefix += cnt[idx];
        }
    }
    if (tid == 1023) off[NS] = prefix;
}

__global__ void scatter_kernel(const int* __restrict__ src, const int* __restrict__ dst,
                               int* __restrict__ cur, int* __restrict__ csr, int n) {
    int i = blockIdx.x * blockDim.x + threadIdx.x;
    if (i < n) {
        int p = atomicAdd(&cur[dst[i]], 1);
        csr[p] = src[i];
    }
}

// weight prep: [Wl;Wr] (256x128 fp32) -> bf16 hi/lo planes
__global__ void prep_w_kernel(const float* __restrict__ Wl, const float* __restrict__ Wr,
                              __nv_bfloat16* __restrict__ wh, __nv_bfloat16* __restrict__ wl) {
    int i = blockIdx.x * blockDim.x + threadIdx.x;
    if (i >= 256 * 128) return;
    float v = (i < 128 * 128) ? Wl[i] : Wr[i - 128 * 128];
    __nv_bfloat16 h = __float2bfloat16_rn(v);
    wh[i] = h;
    wl[i] = __float2bfloat16_rn(v - __bfloat162float(h));
}

// mean aggregation: one warp per node, float4 per lane, 2-edge ILP
__global__ void agg_kernel(const float* __restrict__ x, const int* __restrict__ off,
                           const int* __restrict__ csr, float* __restrict__ out) {
    int node = blockIdx.x * 4 + (threadIdx.x >> 5);
    int lane = threadIdx.x & 31;
    if (node >= NS) return;
    int s = off[node], e = off[node + 1];
    float4 acc = make_float4(0.f, 0.f, 0.f, 0.f);
    int i = s;
    for (; i + 1 < e; i += 2) {
        int s0 = __ldg(&csr[i]);
        int s1 = __ldg(&csr[i + 1]);
        float4 a = *(const float4*)(x + (size_t)s0 * 128 + lane * 4);
        float4 b = *(const float4*)(x + (size_t)s1 * 128 + lane * 4);
        acc.x += a.x + b.x; acc.y += a.y + b.y;
        acc.z += a.z + b.z; acc.w += a.w + b.w;
    }
    if (i < e) {
        int s0 = __ldg(&csr[i]);
        float4 a = *(const float4*)(x + (size_t)s0 * 128 + lane * 4);
        acc.x += a.x; acc.y += a.y; acc.z += a.z; acc.w += a.w;
    }
    float inv = (e > s) ? (1.0f / (float)(e - s)) : 0.0f;
    acc.x *= inv; acc.y *= inv; acc.z *= inv; acc.w *= inv;
    *(float4*)(out + (size_t)node * 128 + lane * 4) = acc;
}

// ================= HMMA (mma.sync bf16) GEMM =================
// out = relu([agg | xin](M x 256) @ [Wl;Wr](256 x 128) + bias)
// per CTA: 128 rows x 128 cols, K=256 as 2 chunks of 128.
// fp32 -> bf16 hi/lo split, 3 passes (hi*hi, hi*lo, lo*hi).
// do_lin: additionally fold final projection out2 = relu_vals @ lin_w + lin_b
//         and skip storing the relu matrix.

#define TC_THREADS 256
// smem byte offsets (row stride 272B = 136 bf16 kills ldmatrix bank conflicts)
#define RS      272
#define SMEM_BIAS_OFF 0
#define SMEM_LW   512
#define SMEM_LIN  1536
#define SMEM_AH   2560
#define SMEM_AL (SMEM_AH + 128 * RS)
#define SMEM_BH (SMEM_AL + 128 * RS)
#define SMEM_BL (SMEM_BH + 128 * RS)
#define SMEM_TOTAL (SMEM_BL + 128 * RS)   // 2560 + 4*34816 = 141824

__device__ __forceinline__ uint32_t smem_u32(const void* p) {
    uint32_t a;
    asm("{ .reg .u64 t; cvta.to.shared.u64 t, %1; cvt.u32.u64 %0, t; }" : "=r"(a) : "l"(p));
    return a;
}

__device__ __forceinline__ uint32_t pack_bf16x2(float lo_val, float hi_val) {
    __nv_bfloat162 h = __floats2bfloat162_rn(lo_val, hi_val);
    return *(uint32_t*)&h;
}

__device__ __forceinline__ void ldsm_x4(uint32_t& r0, uint32_t& r1, uint32_t& r2,
                                        uint32_t& r3, uint32_t addr) {
    asm volatile("ldmatrix.sync.aligned.m8n8.x4.shared.b16 {%0,%1,%2,%3}, [%4];"
                 : "=r"(r0), "=r"(r1), "=r"(r2), "=r"(r3) : "r"(addr));
}

__device__ __forceinline__ void ldsm_x4_t(uint32_t& r0, uint32_t& r1, uint32_t& r2,
                                          uint32_t& r3, uint32_t addr) {
    asm volatile("ldmatrix.sync.aligned.m8n8.x4.trans.shared.b16 {%0,%1,%2,%3}, [%4];"
                 : "=r"(r0), "=r"(r1), "=r"(r2), "=r"(r3) : "r"(addr));
}

__device__ __forceinline__ void mma16816(float* c, uint32_t a0, uint32_t a1, uint32_t a2,
                                         uint32_t a3, uint32_t b0, uint32_t b1) {
    asm volatile(
        "mma.sync.aligned.m16n8k16.row.col.f32.bf16.bf16.f32 "
        "{%0,%1,%2,%3}, {%4,%5,%6,%7}, {%8,%9}, {%0,%1,%2,%3};"
        : "+f"(c[0]), "+f"(c[1]), "+f"(c[2]), "+f"(c[3])
        : "r"(a0), "r"(a1), "r"(a2), "r"(a3), "r"(b0), "r"(b1));
}

__global__ void __launch_bounds__(TC_THREADS, 1)
gemm_mma_kernel(const float* __restrict__ agg, const float* __restrict__ xin,
                const __nv_bfloat16* __restrict__ wh, const __nv_bfloat16* __restrict__ wl,
                const float* __restrict__ bias, float* __restrict__ out, int M,
                int do_lin, const float* __restrict__ lw, const float* __restrict__ lb,
                float* __restrict__ lin_out) {
    extern __shared__ char sm[];
    const uint32_t sb = smem_u32(sm);
    const int tid  = threadIdx.x;
    const int wid  = tid >> 5;
    const int lane = tid & 31;
    const int warp_m = wid & 3;   // 4 row-warps, 32 rows each
    const int warp_n = wid >> 2;  // 2 col-warps, 64 cols each
    const int row0 = blockIdx.x << 7;

    if (tid < 128) ((float*)(sm + SMEM_BIAS_OFF))[tid] = bias[tid];
    if (do_lin && tid < 256) ((float*)(sm + SMEM_LW))[tid] = lw[tid];

    // per-lane ldmatrix address components
    const uint32_t a_lane = (uint32_t)((lane & 15) * RS + ((lane >> 4) << 4));
    const uint32_t b_lane = (uint32_t)((lane & 15) * RS + ((lane >> 4) << 4));
    const uint32_t a_warp = (uint32_t)(warp_m * 32 * RS);   // + mt*16*RS
    const uint32_t b_warp = (uint32_t)(warp_n * 64 * 2);    // + nt*16*2

    float c[2][8][4];
    #pragma unroll
    for (int i = 0; i < 2; i++)
        #pragma unroll
        for (int j = 0; j < 8; j++)
            #pragma unroll
            for (int q = 0; q < 4; q++) c[i][j][q] = 0.f;

    for (int chunk = 0; chunk < 2; chunk++) {
        const float* Asrc = chunk ? xin : agg;
        const __nv_bfloat16* WH = wh + chunk * 128 * 128;
        const __nv_bfloat16* WL = wl + chunk * 128 * 128;

        // stage A: 128 rows x 128 k (hi/lo bf16), float4 loads
        for (int i = tid; i < 128 * 32; i += TC_THREADS) {
            int m  = i >> 5;
            int kk = (i & 31) << 2;
            float4 v = make_float4(0.f, 0.f, 0.f, 0.f);
            if (row0 + m < M)
                v = *(const float4*)(Asrc + (size_t)(row0 + m) * 128 + kk);
            float hx = __bfloat162float(__float2bfloat16_rn(v.x));
            float hy = __bfloat162float(__float2bfloat16_rn(v.y));
            float hz = __bfloat162float(__float2bfloat16_rn(v.z));
            float hw = __bfloat162float(__float2bfloat16_rn(v.w));
            uint32_t off = (uint32_t)(m * RS + kk * 2);
            uint2 hpk, lpk;
            hpk.x = pack_bf16x2(hx, hy);
            hpk.y = pack_bf16x2(hz, hw);
            lpk.x = pack_bf16x2(v.x - hx, v.y - hy);
            lpk.y = pack_bf16x2(v.z - hz, v.w - hw);
            *(uint2*)(sm + SMEM_AH + off) = hpk;
            *(uint2*)(sm + SMEM_AL + off) = lpk;
        }
        // stage B: prebuilt bf16 planes, straight copy (4 bf16 per thread-iter)
        for (int i = tid; i < 128 * 32; i += TC_THREADS) {
            int k = i >> 5;
            int n = (i & 31) << 2;
            uint32_t off = (uint32_t)(k * RS + n * 2);
            *(uint2*)(sm + SMEM_BH + off) = *(const uint2*)(WH + k * 128 + n);
            *(uint2*)(sm + SMEM_BL + off) = *(const uint2*)(WL + k * 128 + n);
        }
        __syncthreads();

        #pragma unroll
        for (int p = 0; p < 3; p++) {
            const uint32_t abuf = sb + ((p == 2) ? SMEM_AL : SMEM_AH);
            const uint32_t bbuf = sb + ((p == 1) ? SMEM_BL : SMEM_BH);
            #pragma unroll
            for (int ks = 0; ks < 8; ks++) {
                uint32_t a[2][4];
                #pragma unroll
                for (int mt = 0; mt < 2; mt++) {
                    uint32_t addr = abuf + a_warp + (uint32_t)(mt * 16 * RS)
                                    + (uint32_t)(ks * 32) + a_lane;
                    ldsm_x4(a[mt][0], a[mt][1], a[mt][2], a[mt][3], addr);
                }
                #pragma unroll
                for (int nt = 0; nt < 4; nt++) {
                    uint32_t b0, b1, b2, b3;
                    uint32_t addr = bbuf + (uint32_t)(ks * 16 * RS) + b_warp
                                    + (uint32_t)(nt * 32) + b_lane;
                    ldsm_x4_t(b0, b1, b2, b3, addr);
                    #pragma unroll
                    for (int mt = 0; mt < 2; mt++) {
                        mma16816(c[mt][nt * 2 + 0], a[mt][0], a[mt][1], a[mt][2], a[mt][3],
                                 b0, b1);
                        mma16816(c[mt][nt * 2 + 1], a[mt][0], a[mt][1], a[mt][2], a[mt][3],
                                 b2, b3);
                    }
                }
            }
        }
        __syncthreads();   // before restage
    }

    // ---- epilogue ----
    const float* sbias = (const float*)(sm + SMEM_BIAS_OFF);
    const float* slw   = (const float*)(sm + SMEM_LW);
    float* slin        = (float*)(sm + SMEM_LIN);   // [128][2]
    const int g = lane >> 2;
    const int t = lane & 3;

    if (!do_lin) {
        #pragma unroll
        for (int nt8 = 0; nt8 < 8; nt8++) {
            int col = warp_n * 64 + nt8 * 8 + t * 2;
            float b0 = sbias[col], b1 = sbias[col + 1];
            #pragma unroll
            for (int mt = 0; mt < 2; mt++) {
                int r_hi = row0 + warp_m * 32 + mt * 16 + g;
                if (r_hi < M) {
                    float2 v;
                    v.x = fmaxf(c[mt][nt8][0] + b0, 0.f);
                    v.y = fmaxf(c[mt][nt8][1] + b1, 0.f);
                    *(float2*)(out + (size_t)r_hi * 128 + col) = v;
                }
                int r_lo = r_hi + 8;
                if (r_lo < M) {
                    float2 v;
                    v.x = fmaxf(c[mt][nt8][2] + b0, 0.f);
                    v.y = fmaxf(c[mt][nt8][3] + b1, 0.f);
                    *(float2*)(out + (size_t)r_lo * 128 + col) = v;
                }
            }
        }
    } else {
        // fold: out2[r] = relu_row(r) @ lin_w + lin_b   (O = 2)
        // partials per thread: 4 rows (mt x {hi,lo}) x 2 outputs
        float pa[2][2][2];   // [mt][h][o]
        #pragma unroll
        for (int mt = 0; mt < 2; mt++)
            #pragma unroll
            for (int h = 0; h < 2; h++) { pa[mt][h][0] = 0.f; pa[mt][h][1] = 0.f; }

        #pragma unroll
        for (int nt8 = 0; nt8 < 8; nt8++) {
            int col = warp_n * 64 + nt8 * 8 + t * 2;
            float b0 = sbias[col], b1 = sbias[col + 1];
            float w00 = slw[(col + 0) * 2 + 0], w01 = slw[(col + 0) * 2 + 1];
            float w10 = slw[(col + 1) * 2 + 0], w11 = slw[(col + 1) * 2 + 1];
            #pragma unroll
            for (int mt = 0; mt < 2; mt++) {
                float vx = fmaxf(c[mt][nt8][0] + b0, 0.f);
                float vy = fmaxf(c[mt][nt8][1] + b1, 0.f);
                pa[mt][0][0] += vx * w00 + vy * w10;
                pa[mt][0][1] += vx * w01 + vy * w11;
                float ux = fmaxf(c[mt][nt8][2] + b0, 0.f);
                float uy = fmaxf(c[mt][nt8][3] + b1, 0.f);
                pa[mt][1][0] += ux * w00 + uy * w10;
                pa[mt][1][1] += ux * w01 + uy * w11;
            }
        }
        // quad reduce (lanes t=0..3 share each row)
        #pragma unroll
        for (int mt = 0; mt < 2; mt++)
            #pragma unroll
            for (int h = 0; h < 2; h++)
                #pragma unroll
                for (int o = 0; o < 2; o++) {
                    float v = pa[mt][h][o];
                    v += __shfl_xor_sync(0xffffffffu, v, 1);
                    v += __shfl_xor_sync(0xffffffffu, v, 2);
                    pa[mt][h][o] = v;
                }
        // exchange between the two col-warps via smem
        if (warp_n == 0 && t == 0) {
            #pragma unroll
            for (int mt = 0; mt < 2; mt++)
                #pragma unroll
                for (int h = 0; h < 2; h++) {
                    int rr = warp_m * 32 + mt * 16 + h * 8 + g;
                    slin[rr * 2 + 0] = pa[mt][h][0];
                    slin[rr * 2 + 1] = pa[mt][h][1];
                }
        }
        __syncthreads();
        if (warp_n == 1 && t == 0) {
            float lb0 = lb[0], lb1 = lb[1];
            #pragma unroll
            for (int mt = 0; mt < 2; mt++)
                #pragma unroll
                for (int h = 0; h < 2; h++) {
                    int rr = warp_m * 32 + mt * 16 + h * 8 + g;
                    int r = row0 + rr;
                    if (r < M) {
                        lin_out[(size_t)r * 2 + 0] = pa[mt][h][0] + slin[rr * 2 + 0] + lb0;
                        lin_out[(size_t)r * 2 + 1] = pa[mt][h][1] + slin[rr * 2 + 1] + lb1;
                    }
                }
        }
    }
}

// ---------------- host launcher ----------------
extern "C" void kernel_launch(void* const* d_in, const int* in_sizes, int n_in,
                              void* d_out, int out_size) {
    const float* x_subject = nullptr;
    const float* wlist[12] = {};
    const float* blist[6]  = {};
    const float* lin_w = nullptr;
    const float* lin_b = nullptr;
    const int*   ss_src = nullptr;
    const int*   ss_dst = nullptr;
    int wc = 0, bc = 0;
    for (int i = 0; i < n_in; i++) {
        int sz = in_sizes[i];
        if      (sz == NS * D)              x_subject = (const float*)d_in[i];
        else if (sz == 128 * 128 && wc < 12) wlist[wc++] = (const float*)d_in[i];
        else if (sz == 128 && bc < 6)        blist[bc++] = (const float*)d_in[i];
        else if (sz == 128 * 2)              lin_w = (const float*)d_in[i];
        else if (sz == 2)                    lin_b = (const float*)d_in[i];
        else if (sz == ESS) {
            if (!ss_src) ss_src = (const int*)d_in[i];
            else         ss_dst = (const int*)d_in[i];
        }
    }
    const float* w1_ss_l = wlist[4];
    const float* w1_ss_r = wlist[5];
    const float* w2_ss_l = wlist[10];
    const float* w2_ss_r = wlist[11];
    const float* b1_ss = blist[2];
    const float* b2_ss = blist[5];

    void *p_cnt, *p_off, *p_cur, *p_csr, *p_agg, *p_s1, *p_wh, *p_wl;
    cudaGetSymbolAddress(&p_cnt, g_cnt);
    cudaGetSymbolAddress(&p_off, g_off);
    cudaGetSymbolAddress(&p_cur, g_cur);
    cudaGetSymbolAddress(&p_csr, g_csr);
    cudaGetSymbolAddress(&p_agg, g_agg);
    cudaGetSymbolAddress(&p_s1,  g_s1);
    cudaGetSymbolAddress(&p_wh,  g_wh);
    cudaGetSymbolAddress(&p_wl,  g_wl);
    int*   cnt = (int*)p_cnt;
    int*   off = (int*)p_off;
    int*   cur = (int*)p_cur;
    int*   csr = (int*)p_csr;
    float* agg = (float*)p_agg;
    float* s1  = (float*)p_s1;
    __nv_bfloat16* wh = (__nv_bfloat16*)p_wh;
    __nv_bfloat16* wl = (__nv_bfloat16*)p_wl;
    float* out = (float*)d_out;

    cudaFuncSetAttribute(gemm_mma_kernel, cudaFuncAttributeMaxDynamicSharedMemorySize,
                         SMEM_TOTAL);

    const int NTILES = (NS + 127) / 128;   // 391

    // ---- CSR build (once; both layers use the same ss edge list) ----
    zero_int_kernel<<<(NS + 255) / 256, 256>>>(cnt, NS);
    hist_kernel<<<(ESS + 255) / 256, 256>>>(ss_dst, cnt, ESS);
    scan_kernel<<<1, 1024>>>(cnt, off, cur);
    scatter_kernel<<<(ESS + 255) / 256, 256>>>(ss_src, ss_dst, cur, csr, ESS);

    // ---- weight prep (bf16 hi/lo planes) ----
    prep_w_kernel<<<128, 256>>>(w1_ss_l, w1_ss_r, wh, wl);
    prep_w_kernel<<<128, 256>>>(w2_ss_l, w2_ss_r, wh + 256 * 128, wl + 256 * 128);

    // ---- layer 1 ----
    agg_kernel<<<(NS + 3) / 4, 128>>>(x_subject, off, csr, agg);
    gemm_mma_kernel<<<NTILES, TC_THREADS, SMEM_TOTAL>>>(
        agg, x_subject, wh, wl, b1_ss, s1, NS, 0, lin_w, lin_b, out);

    // ---- layer 2 (+ fused output projection) ----
    agg_kernel<<<(NS + 3) / 4, 128>>>(s1, off, csr, agg);
    gemm_mma_kernel<<<NTILES, TC_THREADS, SMEM_TOTAL>>>(
        agg, s1, wh + 256 * 128, wl + 256 * 128, b2_ss, s1, NS, 1, lin_w, lin_b, out);
}

// round 5
// speedup vs baseline: 1.7967x; 1.0078x over previous
#include <cuda_runtime.h>
#include <cuda_bf16.h>
#include <cstdint>

// Problem constants (from reference_code)
#define NS   50000
#define D    128
#define H    128
#define ESS  800000

// ---------------- device scratch (static, no allocations) ----------------
__device__ int   g_cnt[NS];
__device__ int   g_off[NS + 1];
__device__ int   g_cur[NS];
__device__ int   g_csr[ESS];
__device__ float g_agg[(size_t)NS * H];
__device__ float g_s1 [(size_t)NS * H];
__device__ __nv_bfloat16 g_wh[2][256 * 128];
__device__ __nv_bfloat16 g_wl[2][256 * 128];

// ---------------- small utility kernels ----------------
__global__ void zero_int_kernel(int* p, int n) {
    int i = blockIdx.x * blockDim.x + threadIdx.x;
    if (i < n) p[i] = 0;
}

__global__ void hist_kernel(const int* __restrict__ dst, int* __restrict__ cnt, int n) {
    int i = blockIdx.x * blockDim.x + threadIdx.x;
    if (i < n) atomicAdd(&cnt[dst[i]], 1);
}

// single-block exclusive scan over NS elements -> offsets + cursor init
__global__ void scan_kernel(const int* __restrict__ cnt, int* __restrict__ off,
                            int* __restrict__ cur) {
    __shared__ int partial[1024];
    const int tid = threadIdx.x;
    const int C = (NS + 1023) / 1024;   // 49
    const int base = tid * C;

    int sum = 0;
    for (int i = 0; i < C; i++) {
        int idx = base + i;
        if (idx < NS) sum += cnt[idx];
    }
    partial[tid] = sum;
    __syncthreads();
    for (int d = 1; d < 1024; d <<= 1) {
        int v = 0;
        if (tid >= d) v = partial[tid - d];
        __syncthreads();
        if (tid >= d) partial[tid] += v;
        __syncthreads();
    }
    int prefix = (tid == 0) ? 0 : partial[tid - 1];
    for (int i = 0; i < C; i++) {
        int idx = base + i;
        if (idx < NS) {
            off[idx] = prefix;
            cur[idx] = prefix;
            prefix += cnt[idx];
        }
    }
    if (tid == 1023) off[NS] = prefix;
}

__global__ void scatter_kernel(const int* __restrict__ src, const int* __restrict__ dst,
                               int* __restrict__ cur, int* __restrict__ csr, int n) {
    int i = blockIdx.x * blockDim.x + threadIdx.x;
    if (i < n) {
        int p = atomicAdd(&cur[dst[i]], 1);
        csr[p] = src[i];
    }
}

// weight prep: both layers' [Wl;Wr] (256x128 fp32) -> bf16 hi/lo planes
__global__ void prep_w_kernel(const float* __restrict__ W1l, const float* __restrict__ W1r,
                              const float* __restrict__ W2l, const float* __restrict__ W2r,
                              __nv_bfloat16* __restrict__ wh, __nv_bfloat16* __restrict__ wl) {
    int i = blockIdx.x * blockDim.x + threadIdx.x;
    if (i >= 2 * 256 * 128) return;
    int layer = i >> 15;          // /(256*128)
    int j = i & 32767;
    const float* Wl = layer ? W2l : W1l;
    const float* Wr = layer ? W2r : W1r;
    float v = (j < 128 * 128) ? Wl[j] : Wr[j - 128 * 128];
    __nv_bfloat16 h = __float2bfloat16_rn(v);
    wh[i] = h;
    wl[i] = __float2bfloat16_rn(v - __bfloat162float(h));
}

// mean aggregation: one warp per node, float4 per lane, 4-edge ILP
__global__ void agg_kernel(const float* __restrict__ x, const int* __restrict__ off,
                           const int* __restrict__ csr, float* __restrict__ out) {
    int node = blockIdx.x * 4 + (threadIdx.x >> 5);
    int lane = threadIdx.x & 31;
    if (node >= NS) return;
    int s = off[node], e = off[node + 1];
    float4 acc = make_float4(0.f, 0.f, 0.f, 0.f);
    int i = s;
    for (; i + 3 < e; i += 4) {
        int s0 = __ldg(&csr[i]);
        int s1 = __ldg(&csr[i + 1]);
        int s2 = __ldg(&csr[i + 2]);
        int s3 = __ldg(&csr[i + 3]);
        float4 a = *(const float4*)(x + (size_t)s0 * 128 + lane * 4);
        float4 b = *(const float4*)(x + (size_t)s1 * 128 + lane * 4);
        float4 cc = *(const float4*)(x + (size_t)s2 * 128 + lane * 4);
        float4 d = *(const float4*)(x + (size_t)s3 * 128 + lane * 4);
        acc.x += (a.x + b.x) + (cc.x + d.x);
        acc.y += (a.y + b.y) + (cc.y + d.y);
        acc.z += (a.z + b.z) + (cc.z + d.z);
        acc.w += (a.w + b.w) + (cc.w + d.w);
    }
    for (; i < e; i++) {
        int s0 = __ldg(&csr[i]);
        float4 a = *(const float4*)(x + (size_t)s0 * 128 + lane * 4);
        acc.x += a.x; acc.y += a.y; acc.z += a.z; acc.w += a.w;
    }
    float inv = (e > s) ? (1.0f / (float)(e - s)) : 0.0f;
    acc.x *= inv; acc.y *= inv; acc.z *= inv; acc.w *= inv;
    *(float4*)(out + (size_t)node * 128 + lane * 4) = acc;
}

// ================= HMMA (mma.sync bf16) persistent GEMM =================
// out = relu([agg | xin](M x 256) @ [Wl;Wr](256 x 128) + bias)
// Persistent: grid = 148 CTAs; B (all 4 bf16 planes) staged ONCE per CTA,
// then loop over 128-row tiles restaging only A.
// fp32 -> bf16 hi/lo split, 3 passes (hi*hi, hi*lo, lo*hi).

#define TC_THREADS 256
#define NSM 148
// smem byte offsets (row stride 272B = 136 bf16 kills ldmatrix bank conflicts)
#define RS      272
#define PLANE   (128 * RS)                 // 34816
#define SMEM_BIAS_OFF 0
#define SMEM_LW   512
#define SMEM_LIN  1536
#define SMEM_B0   2560                     // 4 planes: [c0h, c0l, c1h, c1l]
#define SMEM_AH   (SMEM_B0 + 4 * PLANE)    // 141824
#define SMEM_AL   (SMEM_AH + PLANE)        // 176640
#define SMEM_TOTAL (SMEM_AL + PLANE)       // 211456

__device__ __forceinline__ uint32_t smem_u32(const void* p) {
    uint32_t a;
    asm("{ .reg .u64 t; cvta.to.shared.u64 t, %1; cvt.u32.u64 %0, t; }" : "=r"(a) : "l"(p));
    return a;
}

__device__ __forceinline__ uint32_t pack_bf16x2(float lo_val, float hi_val) {
    __nv_bfloat162 h = __floats2bfloat162_rn(lo_val, hi_val);
    return *(uint32_t*)&h;
}

__device__ __forceinline__ void ldsm_x4(uint32_t& r0, uint32_t& r1, uint32_t& r2,
                                        uint32_t& r3, uint32_t addr) {
    asm volatile("ldmatrix.sync.aligned.m8n8.x4.shared.b16 {%0,%1,%2,%3}, [%4];"
                 : "=r"(r0), "=r"(r1), "=r"(r2), "=r"(r3) : "r"(addr));
}

__device__ __forceinline__ void ldsm_x4_t(uint32_t& r0, uint32_t& r1, uint32_t& r2,
                                          uint32_t& r3, uint32_t addr) {
    asm volatile("ldmatrix.sync.aligned.m8n8.x4.trans.shared.b16 {%0,%1,%2,%3}, [%4];"
                 : "=r"(r0), "=r"(r1), "=r"(r2), "=r"(r3) : "r"(addr));
}

__device__ __forceinline__ void mma16816(float* c, uint32_t a0, uint32_t a1, uint32_t a2,
                                         uint32_t a3, uint32_t b0, uint32_t b1) {
    asm volatile(
        "mma.sync.aligned.m16n8k16.row.col.f32.bf16.bf16.f32 "
        "{%0,%1,%2,%3}, {%4,%5,%6,%7}, {%8,%9}, {%0,%1,%2,%3};"
        : "+f"(c[0]), "+f"(c[1]), "+f"(c[2]), "+f"(c[3])
        : "r"(a0), "r"(a1), "r"(a2), "r"(a3), "r"(b0), "r"(b1));
}

__global__ void __launch_bounds__(TC_THREADS, 1)
gemm_mma_kernel(const float* __restrict__ agg, const float* __restrict__ xin,
                const __nv_bfloat16* __restrict__ wh, const __nv_bfloat16* __restrict__ wl,
                const float* __restrict__ bias, float* __restrict__ out, int M,
                int do_lin, const float* __restrict__ lw, const float* __restrict__ lb,
                float* __restrict__ lin_out) {
    extern __shared__ char sm[];
    const uint32_t sb = smem_u32(sm);
    const int tid  = threadIdx.x;
    const int wid  = tid >> 5;
    const int lane = tid & 31;
    const int warp_m = wid & 3;   // 4 row-warps, 32 rows each
    const int warp_n = wid >> 2;  // 2 col-warps, 64 cols each

    if (tid < 128) ((float*)(sm + SMEM_BIAS_OFF))[tid] = bias[tid];
    if (do_lin && tid < 256) ((float*)(sm + SMEM_LW))[tid] = lw[tid];

    // ---- stage ALL B planes once: [chunk0 hi, chunk0 lo, chunk1 hi, chunk1 lo] ----
    #pragma unroll
    for (int p = 0; p < 4; p++) {
        const __nv_bfloat16* src = ((p & 1) ? wl : wh) + (p >> 1) * 128 * 128;
        char* dstp = sm + SMEM_B0 + p * PLANE;
        for (int i = tid; i < 128 * 32; i += TC_THREADS) {
            int k = i >> 5;
            int n = (i & 31) << 2;
            *(uint2*)(dstp + (uint32_t)(k * RS + n * 2)) = *(const uint2*)(src + k * 128 + n);
        }
    }
    __syncthreads();

    // per-lane ldmatrix address components
    const uint32_t a_lane = (uint32_t)((lane & 15) * RS + ((lane >> 4) << 4));
    const uint32_t b_lane = (uint32_t)((lane & 15) * RS + ((lane >> 4) << 4));
    const uint32_t a_warp = (uint32_t)(warp_m * 32 * RS);   // + mt*16*RS
    const uint32_t b_warp = (uint32_t)(warp_n * 64 * 2);    // + nt*16*2

    const float* sbias = (const float*)(sm + SMEM_BIAS_OFF);
    const float* slw   = (const float*)(sm + SMEM_LW);
    float* slin        = (float*)(sm + SMEM_LIN);   // [128][2]
    const int g = lane >> 2;
    const int t = lane & 3;

    const int ntiles = (M + 127) >> 7;
    for (int tile = blockIdx.x; tile < ntiles; tile += NSM) {
        const int row0 = tile << 7;

        float c[2][8][4];
        #pragma unroll
        for (int i = 0; i < 2; i++)
            #pragma unroll
            for (int j = 0; j < 8; j++)
                #pragma unroll
                for (int q = 0; q < 4; q++) c[i][j][q] = 0.f;

        #pragma unroll
        for (int chunk = 0; chunk < 2; chunk++) {
            const float* Asrc = chunk ? xin : agg;

            // stage A: 128 rows x 128 k (hi/lo bf16), float4 loads
            for (int i = tid; i < 128 * 32; i += TC_THREADS) {
                int m  = i >> 5;
                int kk = (i & 31) << 2;
                float4 v = make_float4(0.f, 0.f, 0.f, 0.f);
                if (row0 + m < M)
                    v = *(const float4*)(Asrc + (size_t)(row0 + m) * 128 + kk);
                float hx = __bfloat162float(__float2bfloat16_rn(v.x));
                float hy = __bfloat162float(__float2bfloat16_rn(v.y));
                float hz = __bfloat162float(__float2bfloat16_rn(v.z));
                float hw = __bfloat162float(__float2bfloat16_rn(v.w));
                uint32_t off = (uint32_t)(m * RS + kk * 2);
                uint2 hpk, lpk;
                hpk.x = pack_bf16x2(hx, hy);
                hpk.y = pack_bf16x2(hz, hw);
                lpk.x = pack_bf16x2(v.x - hx, v.y - hy);
                lpk.y = pack_bf16x2(v.z - hz, v.w - hw);
                *(uint2*)(sm + SMEM_AH + off) = hpk;
                *(uint2*)(sm + SMEM_AL + off) = lpk;
            }
            __syncthreads();

            const uint32_t bh_base = sb + SMEM_B0 + (uint32_t)(chunk * 2) * PLANE;
            #pragma unroll
            for (int p = 0; p < 3; p++) {
                const uint32_t abuf = sb + ((p == 2) ? SMEM_AL : SMEM_AH);
                const uint32_t bbuf = bh_base + ((p == 1) ? PLANE : 0u);
                #pragma unroll
                for (int ks = 0; ks < 8; ks++) {
                    uint32_t a[2][4];
                    #pragma unroll
                    for (int mt = 0; mt < 2; mt++) {
                        uint32_t addr = abuf + a_warp + (uint32_t)(mt * 16 * RS)
                                        + (uint32_t)(ks * 32) + a_lane;
                        ldsm_x4(a[mt][0], a[mt][1], a[mt][2], a[mt][3], addr);
                    }
                    #pragma unroll
                    for (int nt = 0; nt < 4; nt++) {
                        uint32_t b0, b1, b2, b3;
                        uint32_t addr = bbuf + (uint32_t)(ks * 16 * RS) + b_warp
                                        + (uint32_t)(nt * 32) + b_lane;
                        ldsm_x4_t(b0, b1, b2, b3, addr);
                        #pragma unroll
                        for (int mt = 0; mt < 2; mt++) {
                            mma16816(c[mt][nt * 2 + 0], a[mt][0], a[mt][1], a[mt][2],
                                     a[mt][3], b0, b1);
                            mma16816(c[mt][nt * 2 + 1], a[mt][0], a[mt][1], a[mt][2],
                                     a[mt][3], b2, b3);
                        }
                    }
                }
            }
            __syncthreads();   // A consumed; safe to restage
        }

        // ---- epilogue ----
        if (!do_lin) {
            #pragma unroll
            for (int nt8 = 0; nt8 < 8; nt8++) {
                int col = warp_n * 64 + nt8 * 8 + t * 2;
                float b0 = sbias[col], b1 = sbias[col + 1];
                #pragma unroll
                for (int mt = 0; mt < 2; mt++) {
                    int r_hi = row0 + warp_m * 32 + mt * 16 + g;
                    if (r_hi < M) {
                        float2 v;
                        v.x = fmaxf(c[mt][nt8][0] + b0, 0.f);
                        v.y = fmaxf(c[mt][nt8][1] + b1, 0.f);
                        *(float2*)(out + (size_t)r_hi * 128 + col) = v;
                    }
                    int r_lo = r_hi + 8;
                    if (r_lo < M) {
                        float2 v;
                        v.x = fmaxf(c[mt][nt8][2] + b0, 0.f);
                        v.y = fmaxf(c[mt][nt8][3] + b1, 0.f);
                        *(float2*)(out + (size_t)r_lo * 128 + col) = v;
                    }
                }
            }
        } else {
            // fold: out2[r] = relu_row(r) @ lin_w + lin_b   (O = 2)
            float pa[2][2][2];   // [mt][h][o]
            #pragma unroll
            for (int mt = 0; mt < 2; mt++)
                #pragma unroll
                for (int h = 0; h < 2; h++) { pa[mt][h][0] = 0.f; pa[mt][h][1] = 0.f; }

            #pragma unroll
            for (int nt8 = 0; nt8 < 8; nt8++) {
                int col = warp_n * 64 + nt8 * 8 + t * 2;
                float b0 = sbias[col], b1 = sbias[col + 1];
                float w00 = slw[(col + 0) * 2 + 0], w01 = slw[(col + 0) * 2 + 1];
                float w10 = slw[(col + 1) * 2 + 0], w11 = slw[(col + 1) * 2 + 1];
                #pragma unroll
                for (int mt = 0; mt < 2; mt++) {
                    float vx = fmaxf(c[mt][nt8][0] + b0, 0.f);
                    float vy = fmaxf(c[mt][nt8][1] + b1, 0.f);
                    pa[mt][0][0] += vx * w00 + vy * w10;
                    pa[mt][0][1] += vx * w01 + vy * w11;
                    float ux = fmaxf(c[mt][nt8][2] + b0, 0.f);
                    float uy = fmaxf(c[mt][nt8][3] + b1, 0.f);
                    pa[mt][1][0] += ux * w00 + uy * w10;
                    pa[mt][1][1] += ux * w01 + uy * w11;
                }
            }
            #pragma unroll
            for (int mt = 0; mt < 2; mt++)
                #pragma unroll
                for (int h = 0; h < 2; h++)
                    #pragma unroll
                    for (int o = 0; o < 2; o++) {
                        float v = pa[mt][h][o];
                        v += __shfl_xor_sync(0xffffffffu, v, 1);
                        v += __shfl_xor_sync(0xffffffffu, v, 2);
                        pa[mt][h][o] = v;
                    }
            if (warp_n == 0 && t == 0) {
                #pragma unroll
                for (int mt = 0; mt < 2; mt++)
                    #pragma unroll
                    for (int h = 0; h < 2; h++) {
                        int rr = warp_m * 32 + mt * 16 + h * 8 + g;
                        slin[rr * 2 + 0] = pa[mt][h][0];
                        slin[rr * 2 + 1] = pa[mt][h][1];
                    }
            }
            __syncthreads();
            if (warp_n == 1 && t == 0) {
                float lb0 = lb[0], lb1 = lb[1];
                #pragma unroll
                for (int mt = 0; mt < 2; mt++)
                    #pragma unroll
                    for (int h = 0; h < 2; h++) {
                        int rr = warp_m * 32 + mt * 16 + h * 8 + g;
                        int r = row0 + rr;
                        if (r < M) {
                            lin_out[(size_t)r * 2 + 0] = pa[mt][h][0] + slin[rr * 2 + 0] + lb0;
                            lin_out[(size_t)r * 2 + 1] = pa[mt][h][1] + slin[rr * 2 + 1] + lb1;
                        }
                    }
            }
            __syncthreads();   // slin consumed before next tile's epilogue writes
        }
    }
}

// ---------------- host launcher ----------------
extern "C" void kernel_launch(void* const* d_in, const int* in_sizes, int n_in,
                              void* d_out, int out_size) {
    const float* x_subject = nullptr;
    const float* wlist[12] = {};
    const float* blist[6]  = {};
    const float* lin_w = nullptr;
    const float* lin_b = nullptr;
    const int*   ss_src = nullptr;
    const int*   ss_dst = nullptr;
    int wc = 0, bc = 0;
    for (int i = 0; i < n_in; i++) {
        int sz = in_sizes[i];
        if      (sz == NS * D)              x_subject = (const float*)d_in[i];
        else if (sz == 128 * 128 && wc < 12) wlist[wc++] = (const float*)d_in[i];
        else if (sz == 128 && bc < 6)        blist[bc++] = (const float*)d_in[i];
        else if (sz == 128 * 2)              lin_w = (const float*)d_in[i];
        else if (sz == 2)                    lin_b = (const float*)d_in[i];
        else if (sz == ESS) {
            if (!ss_src) ss_src = (const int*)d_in[i];
            else         ss_dst = (const int*)d_in[i];
        }
    }
    const float* w1_ss_l = wlist[4];
    const float* w1_ss_r = wlist[5];
    const float* w2_ss_l = wlist[10];
    const float* w2_ss_r = wlist[11];
    const float* b1_ss = blist[2];
    const float* b2_ss = blist[5];

    void *p_cnt, *p_off, *p_cur, *p_csr, *p_agg, *p_s1, *p_wh, *p_wl;
    cudaGetSymbolAddress(&p_cnt, g_cnt);
    cudaGetSymbolAddress(&p_off, g_off);
    cudaGetSymbolAddress(&p_cur, g_cur);
    cudaGetSymbolAddress(&p_csr, g_csr);
    cudaGetSymbolAddress(&p_agg, g_agg);
    cudaGetSymbolAddress(&p_s1,  g_s1);
    cudaGetSymbolAddress(&p_wh,  g_wh);
    cudaGetSymbolAddress(&p_wl,  g_wl);
    int*   cnt = (int*)p_cnt;
    int*   off = (int*)p_off;
    int*   cur = (int*)p_cur;
    int*   csr = (int*)p_csr;
    float* agg = (float*)p_agg;
    float* s1  = (float*)p_s1;
    __nv_bfloat16* wh = (__nv_bfloat16*)p_wh;
    __nv_bfloat16* wl = (__nv_bfloat16*)p_wl;
    float* out = (float*)d_out;

    cudaFuncSetAttribute(gemm_mma_kernel, cudaFuncAttributeMaxDynamicSharedMemorySize,
                         SMEM_TOTAL);

    // ---- CSR build (once; both layers use the same ss edge list) ----
    zero_int_kernel<<<(NS + 255) / 256, 256>>>(cnt, NS);
    hist_kernel<<<(ESS + 255) / 256, 256>>>(ss_dst, cnt, ESS);
    scan_kernel<<<1, 1024>>>(cnt, off, cur);
    scatter_kernel<<<(ESS + 255) / 256, 256>>>(ss_src, ss_dst, cur, csr, ESS);

    // ---- weight prep (bf16 hi/lo planes, both layers) ----
    prep_w_kernel<<<256, 256>>>(w1_ss_l, w1_ss_r, w2_ss_l, w2_ss_r, wh, wl);

    // ---- layer 1 ----
    agg_kernel<<<(NS + 3) / 4, 128>>>(x_subject, off, csr, agg);
    gemm_mma_kernel<<<NSM, TC_THREADS, SMEM_TOTAL>>>(
        agg, x_subject, wh, wl, b1_ss, s1, NS, 0, lin_w, lin_b, out);

    // ---- layer 2 (+ fused output projection) ----
    agg_kernel<<<(NS + 3) / 4, 128>>>(s1, off, csr, agg);
    gemm_mma_kernel<<<NSM, TC_THREADS, SMEM_TOTAL>>>(
        agg, s1, wh + 2 * 128 * 128, wl + 2 * 128 * 128, b2_ss, s1, NS, 1, lin_w, lin_b, out);
}